// round 11
// baseline (speedup 1.0000x reference)
#include <cuda_runtime.h>
#include <math.h>
#include <stdint.h>

#define N_NODES 10000
#define N_EDGES 640000
#define HD      128
#define NHEADS  8
#define TILE    128                 // k_proj tile
#define TILE_M  32                  // k_edge tile (per quarter-pipeline)
#define NTILES32 (N_EDGES / TILE_M) // 20000
#define EDGE_GRID 148
#define SA_STRIDE 132               // scalar-LDS tiles
#define SW_STRIDE 136               // permuted W for LDS.64 B-fragments

// scratch (allocation-free rule: __device__ globals)
__device__ float g_Q[N_NODES * HD];
__device__ float g_K[N_NODES * HD];
__device__ float g_V[N_NODES * HD];
__device__ float g_Z[N_NODES * NHEADS];
// dst-sort scratch
__device__ int g_cnt[N_NODES];
__device__ int g_pos[N_NODES];
__device__ int g_perm[N_EDGES];
__device__ int g_srcs[N_EDGES];
__device__ int g_dsts[N_EDGES];

// edge smem: sWp[128][136] + 8 e-bufs[32][132] + hS[4][32*8] + sBe[128] + idx[4][4][96]
#define SMEM_EDGE ((128 * SW_STRIDE + 8 * TILE_M * SA_STRIDE + 4 * TILE_M * NHEADS + 128) * 4 \
                   + 4 * 4 * 96 * 4)
#define SMEM_PROJ ((2 * TILE * SA_STRIDE + 128) * 4)

extern __shared__ char smem_raw[];

__device__ __forceinline__ float cvt_tf32(float x) {
    unsigned u;
    asm("cvt.rna.tf32.f32 %0, %1;" : "=r"(u) : "f"(x));
    return __uint_as_float(u);
}

__device__ __forceinline__ void mma_tf32(float c[4],
                                         unsigned a0, unsigned a1, unsigned a2, unsigned a3,
                                         unsigned b0, unsigned b1) {
    asm volatile(
        "mma.sync.aligned.m16n8k8.row.col.f32.tf32.tf32.f32 "
        "{%0,%1,%2,%3}, {%4,%5,%6,%7}, {%8,%9}, {%0,%1,%2,%3};"
        : "+f"(c[0]), "+f"(c[1]), "+f"(c[2]), "+f"(c[3])
        : "r"(a0), "r"(a1), "r"(a2), "r"(a3), "r"(b0), "r"(b1));
}

template <int NT>
__device__ __forceinline__ void load_tile_tf32(float* dst, const float* __restrict__ src,
                                               int rows, int tid) {
    for (int idx = tid; idx < TILE * 32; idx += NT) {
        int row = idx >> 5, q = idx & 31;
        float4 v = make_float4(0.f, 0.f, 0.f, 0.f);
        if (row < rows) v = ((const float4*)(src + (size_t)row * 128))[q];
        float4 o = make_float4(cvt_tf32(v.x), cvt_tf32(v.y), cvt_tf32(v.z), cvt_tf32(v.w));
        *((float4*)(dst + row * SA_STRIDE + q * 4)) = o;
    }
}

__device__ __forceinline__ void bar_q(int q) {
    asm volatile("bar.sync %0, 128;" :: "r"(q + 1) : "memory");
}

// load idx triplet (perm, src, dst) for sorted tile T into a 96-int slot
__device__ __forceinline__ void ldg_idx(int* slot, int T, int qtid) {
    if (T >= NTILES32) return;
    int base = T * TILE_M;
    if (qtid < 32) slot[qtid] = g_perm[base + qtid];
    else if (qtid < 64) slot[qtid] = g_srcs[base + (qtid - 32)];
    else if (qtid < 96) slot[qtid] = g_dsts[base + (qtid - 64)];
}

// cp.async 32 permuted e-rows (512B each) into [32][SA_STRIDE], 128 threads
__device__ __forceinline__ void cp_rows(float* sDst, const int* slot,
                                        const float* __restrict__ e, int qtid) {
    int row = qtid >> 2, part = qtid & 3;
    const float* g = e + (size_t)slot[row] * 128 + part * 32;
    float* s = sDst + row * SA_STRIDE + part * 32;
#pragma unroll
    for (int c = 0; c < 8; c++) {
        unsigned sa = (unsigned)__cvta_generic_to_shared(s + c * 4);
        asm volatile("cp.async.cg.shared.global [%0], [%1], 16;\n"
                     :: "r"(sa), "l"(g + c * 4));
    }
}

// ---------------- kernel 0: zero out + z + counters ----------------------
__global__ void k_zero(float* __restrict__ out) {
    int i = blockIdx.x * blockDim.x + threadIdx.x;
    const int n_out4 = N_NODES * HD / 4;
    const int n_z4 = N_NODES * NHEADS / 4;
    const int n_c4 = N_NODES / 4;
    float4 z = make_float4(0.f, 0.f, 0.f, 0.f);
    if (i < n_out4) ((float4*)out)[i] = z;
    else if (i < n_out4 + n_z4) ((float4*)g_Z)[i - n_out4] = z;
    else if (i < n_out4 + n_z4 + n_c4) ((float4*)g_cnt)[i - n_out4 - n_z4] = z;
}

// ---------------- sort kernels -------------------------------------------
__global__ void k_hist(const int* __restrict__ dst) {
    int i = blockIdx.x * blockDim.x + threadIdx.x;
    if (i < N_EDGES) atomicAdd(&g_cnt[dst[i]], 1);
}

__global__ void k_scan() {
    __shared__ int sums[1024];
    int t = threadIdx.x;
    int s = 0;
    if (t < 1000) {
        int base = t * 10;
#pragma unroll
        for (int j = 0; j < 10; j++) s += g_cnt[base + j];
    }
    sums[t] = s;
    __syncthreads();
    for (int off = 1; off < 1024; off <<= 1) {
        int v = (t >= off) ? sums[t - off] : 0;
        __syncthreads();
        sums[t] += v;
        __syncthreads();
    }
    if (t < 1000) {
        int run = (t == 0) ? 0 : sums[t - 1];
        int base = t * 10;
#pragma unroll
        for (int j = 0; j < 10; j++) { g_pos[base + j] = run; run += g_cnt[base + j]; }
    }
}

__global__ void k_place(const int* __restrict__ src, const int* __restrict__ dst) {
    int i = blockIdx.x * blockDim.x + threadIdx.x;
    if (i >= N_EDGES) return;
    int d = dst[i];
    int p = atomicAdd(&g_pos[d], 1);
    g_perm[p] = i;
    g_srcs[p] = src[i];
    g_dsts[p] = d;
}

// ---------------- kernel 1: QKV projections ------------------------------
__global__ void __launch_bounds__(512, 1)
k_proj(const float* __restrict__ h,
       const float* __restrict__ Wq, const float* __restrict__ bq,
       const float* __restrict__ Wk, const float* __restrict__ bk,
       const float* __restrict__ Wv, const float* __restrict__ bv) {
    float* smem = (float*)smem_raw;
    float* sA = smem;
    float* sB = sA + TILE * SA_STRIDE;
    float* sBias = sB + TILE * SA_STRIDE;

    const float* W; const float* b; float* outp;
    if (blockIdx.y == 0)      { W = Wq; b = bq; outp = g_Q; }
    else if (blockIdx.y == 1) { W = Wk; b = bk; outp = g_K; }
    else                      { W = Wv; b = bv; outp = g_V; }

    int tid = threadIdx.x;
    int lane = tid & 31, wid = tid >> 5;
    int warp_m = wid & 3, warp_n = wid >> 2;
    int node0 = blockIdx.x * TILE;
    int rows = N_NODES - node0; if (rows > TILE) rows = TILE;

    if (tid < 128) sBias[tid] = b[tid];
    load_tile_tf32<512>(sA, h + (size_t)node0 * 128, rows, tid);
    load_tile_tf32<512>(sB, W, 128, tid);
    __syncthreads();

    float acc[2][4][4];
#pragma unroll
    for (int mt = 0; mt < 2; mt++)
#pragma unroll
        for (int nt = 0; nt < 4; nt++)
#pragma unroll
            for (int i = 0; i < 4; i++) acc[mt][nt][i] = 0.f;

    int gid = lane >> 2, tig = lane & 3;
#pragma unroll
    for (int kk = 0; kk < 16; kk++) {
        int k0 = kk * 8;
        unsigned a[2][4];
#pragma unroll
        for (int mt = 0; mt < 2; mt++) {
            int r = warp_m * 32 + mt * 16 + gid;
            a[mt][0] = __float_as_uint(sA[r * SA_STRIDE + k0 + tig]);
            a[mt][1] = __float_as_uint(sA[(r + 8) * SA_STRIDE + k0 + tig]);
            a[mt][2] = __float_as_uint(sA[r * SA_STRIDE + k0 + tig + 4]);
            a[mt][3] = __float_as_uint(sA[(r + 8) * SA_STRIDE + k0 + tig + 4]);
        }
#pragma unroll
        for (int nt = 0; nt < 4; nt++) {
            int c = warp_n * 32 + nt * 8 + gid;
            unsigned b0 = __float_as_uint(sB[c * SA_STRIDE + k0 + tig]);
            unsigned b1 = __float_as_uint(sB[c * SA_STRIDE + k0 + tig + 4]);
            mma_tf32(acc[0][nt], a[0][0], a[0][1], a[0][2], a[0][3], b0, b1);
            mma_tf32(acc[1][nt], a[1][0], a[1][1], a[1][2], a[1][3], b0, b1);
        }
    }

#pragma unroll
    for (int nt = 0; nt < 4; nt++) {
        int c = warp_n * 32 + nt * 8 + 2 * tig;
        float b0 = sBias[c], b1 = sBias[c + 1];
#pragma unroll
        for (int mt = 0; mt < 2; mt++) {
            int r0 = warp_m * 32 + mt * 16 + gid;
            if (r0 < rows)
                *((float2*)(outp + (size_t)(node0 + r0) * 128 + c)) =
                    make_float2(acc[mt][nt][0] + b0, acc[mt][nt][1] + b1);
            int r1 = r0 + 8;
            if (r1 < rows)
                *((float2*)(outp + (size_t)(node0 + r1) * 128 + c)) =
                    make_float2(acc[mt][nt][2] + b0, acc[mt][nt][3] + b1);
        }
    }
}

// ---------------- kernel 2: dst-sorted quad-pipeline edge kernel ---------
// 512 threads = four independent 128-thread quarters on private 32-edge tile
// streams (named barriers). Edges pre-sorted by dst: scatter/z become
// run-length accumulations; score phase uses coalesced row-major K/Q reads.
__global__ void __launch_bounds__(512, 1)
k_edge(const float* __restrict__ e, const float* __restrict__ We,
       const float* __restrict__ be, float* __restrict__ out) {
    float* smem = (float*)smem_raw;
    float* sWp = smem;                              // [128][136] tf32, pair-permuted
    float* sEb = sWp + 128 * SW_STRIDE;             // 8 bufs [32][132]
    float* sSb = sEb + 8 * TILE_M * SA_STRIDE;      // [4][32*8]
    float* sBe = sSb + 4 * TILE_M * NHEADS;         // [128]
    int* sIdxB = (int*)(sBe + 128);                 // [4][4][96]

    int tid = threadIdx.x;
    int qtr = tid >> 7, qtid = tid & 127;
    int lane = tid & 31;
    int warp = qtid >> 5;                           // 0..3 within quarter
    int gid = lane >> 2, tig = lane & 3;

    // permuted W (cols (k, k+4) adjacent -> LDS.64) + be
    for (int idx = tid; idx < 128 * 128; idx += 512) {
        int row = idx >> 7, col = idx & 127;
        int pc = (col & ~7) | ((col & 3) << 1) | ((col >> 2) & 1);
        sWp[row * SW_STRIDE + pc] = cvt_tf32(We[idx]);
    }
    if (tid < 128) sBe[tid] = be[tid];
    __syncthreads();   // last block-wide sync; quarters independent below

    float* hE = sEb + qtr * 2 * TILE_M * SA_STRIDE;
    float* hS = sSb + qtr * TILE_M * NHEADS;
    int* hIdx = sIdxB + qtr * 4 * 96;

    const int stride = gridDim.x * 4;
    const int p0 = blockIdx.x * 4 + qtr;

    // prologue: idx t0 -> e t0 -> idx t1 -> e t1 -> idx t2
    ldg_idx(hIdx, p0, qtid);
    bar_q(qtr);
    if (p0 < NTILES32) cp_rows(hE, hIdx, e, qtid);
    asm volatile("cp.async.commit_group;" ::: "memory");
    ldg_idx(hIdx + 96, p0 + stride, qtid);
    bar_q(qtr);
    if (p0 + stride < NTILES32) cp_rows(hE + TILE_M * SA_STRIDE, hIdx + 96, e, qtid);
    asm volatile("cp.async.commit_group;" ::: "memory");
    ldg_idx(hIdx + 2 * 96, p0 + 2 * stride, qtid);

    int k = 0;
    for (int t = p0; t < NTILES32; t += stride, k++) {
        asm volatile("cp.async.wait_group 1;" ::: "memory");
        bar_q(qtr);   // e tile t resident; idx slots settled

        float* sE = hE + (k & 1) * TILE_M * SA_STRIDE;
        int* slot = hIdx + (k & 3) * 96;

        // 32x128x128 GEMM: E = e_tile @ We^T (A raw fp32 -> tf32 truncation)
        float acc[2][4][4];
#pragma unroll
        for (int mt = 0; mt < 2; mt++)
#pragma unroll
            for (int nt = 0; nt < 4; nt++)
#pragma unroll
                for (int i = 0; i < 4; i++) acc[mt][nt][i] = 0.f;

#pragma unroll
        for (int kk = 0; kk < 16; kk++) {
            int k0 = kk * 8;
            unsigned a[2][4];
#pragma unroll
            for (int mt = 0; mt < 2; mt++) {
                int r = mt * 16 + gid;
                a[mt][0] = __float_as_uint(sE[r * SA_STRIDE + k0 + tig]);
                a[mt][1] = __float_as_uint(sE[(r + 8) * SA_STRIDE + k0 + tig]);
                a[mt][2] = __float_as_uint(sE[r * SA_STRIDE + k0 + tig + 4]);
                a[mt][3] = __float_as_uint(sE[(r + 8) * SA_STRIDE + k0 + tig + 4]);
            }
#pragma unroll
            for (int nt = 0; nt < 4; nt++) {
                int c = warp * 32 + nt * 8 + gid;
                float2 bv = *(const float2*)(sWp + c * SW_STRIDE + k0 + 2 * tig);
                mma_tf32(acc[0][nt], a[0][0], a[0][1], a[0][2], a[0][3],
                         __float_as_uint(bv.x), __float_as_uint(bv.y));
                mma_tf32(acc[1][nt], a[1][0], a[1][1], a[1][2], a[1][3],
                         __float_as_uint(bv.x), __float_as_uint(bv.y));
            }
        }
        bar_q(qtr);   // all A-reads of sE complete; safe to overwrite

        // stage E+be into sE (row-major, fragment layout -> rows)
#pragma unroll
        for (int nt = 0; nt < 4; nt++) {
            int c = warp * 32 + nt * 8 + 2 * tig;
            float b0 = sBe[c], b1 = sBe[c + 1];
#pragma unroll
            for (int mt = 0; mt < 2; mt++) {
                int r0 = mt * 16 + gid;
                *(float2*)(sE + r0 * SA_STRIDE + c) =
                    make_float2(acc[mt][nt][0] + b0, acc[mt][nt][1] + b1);
                *(float2*)(sE + (r0 + 8) * SA_STRIDE + c) =
                    make_float2(acc[mt][nt][2] + b0, acc[mt][nt][3] + b1);
            }
        }
        bar_q(qtr);   // staged E visible

        // score: coalesced K/Q row reads (4 rows/warp, 8 lanes/row = 128B lines)
        {
            int rg4 = lane >> 3, chunk = lane & 7;
#pragma unroll
            for (int round = 0; round < 2; round++) {
                int r = round * 16 + warp * 4 + rg4;
                int sN = slot[32 + r], dN = slot[64 + r];
                const float4* Kp = (const float4*)(g_K + (size_t)sN * 128);
                const float4* Qp = (const float4*)(g_Q + (size_t)dN * 128);
                float p[4];
#pragma unroll
                for (int j = 0; j < 4; j++) {
                    float4 kv = Kp[j * 8 + chunk];
                    float4 qv = Qp[j * 8 + chunk];
                    float4 ev = *(const float4*)(sE + r * SA_STRIDE + j * 32 + chunk * 4);
                    p[j] = kv.x * qv.x * ev.x + kv.y * qv.y * ev.y
                         + kv.z * qv.z * ev.z + kv.w * qv.w * ev.w;
                }
                // lanes chunk=0..7 cover head pairs: head(j, chunk) = 2*j + (chunk>>2)
#pragma unroll
                for (int j = 0; j < 4; j++) {
                    p[j] += __shfl_xor_sync(0xffffffffu, p[j], 1);
                    p[j] += __shfl_xor_sync(0xffffffffu, p[j], 2);
                }
                if ((lane & 3) == 0) {
                    int b = chunk >> 2;
#pragma unroll
                    for (int j = 0; j < 4; j++) {
                        float s = __expf(fminf(fmaxf(p[j] * 0.25f, -5.f), 5.f));
                        hS[r * NHEADS + 2 * j + b] = s;
                    }
                }
            }
        }
        bar_q(qtr);   // hS visible; sE free for prefetch

        // prefetch e rows of t+2 into freed buffer; idx t+3 into its slot
        int t2 = t + 2 * stride;
        if (t2 < NTILES32) cp_rows(sE, hIdx + ((k + 2) & 3) * 96, e, qtid);
        asm volatile("cp.async.commit_group;" ::: "memory");
        ldg_idx(hIdx + ((k + 3) & 3) * 96, t + 3 * stride, qtid);

        // z run-length accumulation (8 threads, one per head)
        if (qtid < 8) {
            int h = qtid;
            float za = 0.f;
            int curd = slot[64];
#pragma unroll
            for (int r = 0; r < 32; r++) {
                int d = slot[64 + r];
                if (d != curd) { atomicAdd(&g_Z[(size_t)curd * NHEADS + h], za); za = 0.f; curd = d; }
                za += hS[r * NHEADS + h];
            }
            atomicAdd(&g_Z[(size_t)curd * NHEADS + h], za);
        }

        // scatter: run-length accumulate s*V per dst, flush on run boundary
        {
            int rg = qtid >> 5, q4 = qtid & 31, h4 = q4 >> 2;
            int r0 = rg * 8;
            int curd = slot[64 + r0];
            float4 a4 = make_float4(0.f, 0.f, 0.f, 0.f);
#pragma unroll
            for (int rr = 0; rr < 8; rr++) {
                int r = r0 + rr;
                int d = slot[64 + r];
                if (d != curd) {
                    atomicAdd((float4*)(out + (size_t)curd * 128 + q4 * 4), a4);
                    a4 = make_float4(0.f, 0.f, 0.f, 0.f);
                    curd = d;
                }
                float sc = hS[r * NHEADS + h4];
                float4 v = ((const float4*)(g_V + (size_t)slot[32 + r] * 128))[q4];
                a4.x += sc * v.x; a4.y += sc * v.y; a4.z += sc * v.z; a4.w += sc * v.w;
            }
            atomicAdd((float4*)(out + (size_t)curd * 128 + q4 * 4), a4);
        }
    }
}

// ---------------- kernel 3: normalize ------------------------------------
__global__ void k_final(float* __restrict__ out) {
    int i = blockIdx.x * blockDim.x + threadIdx.x;
    if (i >= N_NODES * HD / 4) return;
    int node = i >> 5;
    int head = (i & 31) >> 2;
    float z = 1.0f / (g_Z[node * NHEADS + head] + 1e-6f);
    float4 v = ((float4*)out)[i];
    v.x *= z; v.y *= z; v.z *= z; v.w *= z;
    ((float4*)out)[i] = v;
}

// ---------------- launcher ------------------------------------------------
extern "C" void kernel_launch(void* const* d_in, const int* in_sizes, int n_in,
                              void* d_out, int out_size) {
    (void)in_sizes; (void)n_in; (void)out_size;
    const float* h  = (const float*)d_in[0];
    const float* e  = (const float*)d_in[1];
    const int*   src = (const int*)d_in[2];
    const int*   dst = (const int*)d_in[3];
    const float* Wq = (const float*)d_in[4];
    const float* bq = (const float*)d_in[5];
    const float* Wk = (const float*)d_in[6];
    const float* bk = (const float*)d_in[7];
    const float* We = (const float*)d_in[8];
    const float* be = (const float*)d_in[9];
    const float* Wv = (const float*)d_in[10];
    const float* bv = (const float*)d_in[11];
    float* out = (float*)d_out;

    cudaFuncSetAttribute(k_proj, cudaFuncAttributeMaxDynamicSharedMemorySize, SMEM_PROJ);
    cudaFuncSetAttribute(k_edge, cudaFuncAttributeMaxDynamicSharedMemorySize, SMEM_EDGE);

    const int nz = N_NODES * HD / 4 + N_NODES * NHEADS / 4 + N_NODES / 4;
    k_zero<<<(nz + 255) / 256, 256>>>(out);
    k_hist<<<(N_EDGES + 255) / 256, 256>>>(dst);
    k_scan<<<1, 1024>>>();
    k_place<<<(N_EDGES + 255) / 256, 256>>>(src, dst);
    k_proj<<<dim3((N_NODES + TILE - 1) / TILE, 3), 512, SMEM_PROJ>>>(h, Wq, bq, Wk, bk, Wv, bv);
    k_edge<<<EDGE_GRID, 512, SMEM_EDGE>>>(e, We, be, out);
    k_final<<<(N_NODES * HD / 4 + 255) / 256, 256>>>(out);
}

// round 12
// speedup vs baseline: 1.2333x; 1.2333x over previous
#include <cuda_runtime.h>
#include <cuda_fp16.h>
#include <math.h>
#include <stdint.h>

#define N_NODES 10000
#define N_EDGES 640000
#define HD      128
#define NHEADS  8
#define TILE    128                 // k_proj tile
#define TILE_M  32                  // k_edge tile (per quarter-pipeline)
#define NTILES32 (N_EDGES / TILE_M) // 20000
#define EDGE_GRID 148
#define SA_STRIDE 132               // k_proj tf32 tiles
#define SE_STRIDE 136               // e bufs: 544B ≡ 32B mod 128 -> LDS.64 conflict-free
#define SWH_STRIDE 144              // fp16 W: 288B ≡ 32B mod 128 -> LDS.64 conflict-free

// scratch (allocation-free rule: __device__ globals)
__device__ float g_Q[N_NODES * HD];
__device__ float g_K[N_NODES * HD];
__device__ float g_V[N_NODES * HD];
__device__ float g_Z[N_NODES * NHEADS];

// edge smem: 8 e-bufs[32][136] f32 + sS[4][32*8] + sBe[128] + sWh[128][144] half + idx[4][4][64]
#define SMEM_EDGE (8 * TILE_M * SE_STRIDE * 4 + 4 * TILE_M * NHEADS * 4 + 128 * 4 \
                   + 128 * SWH_STRIDE * 2 + 4 * 4 * 64 * 4)
#define SMEM_PROJ ((2 * TILE * SA_STRIDE + 128) * 4)

extern __shared__ char smem_raw[];

__device__ __forceinline__ float cvt_tf32(float x) {
    unsigned u;
    asm("cvt.rna.tf32.f32 %0, %1;" : "=r"(u) : "f"(x));
    return __uint_as_float(u);
}

// pack two fp32 into half2 (lo = f.x = lower k index)
__device__ __forceinline__ unsigned cvt_h2(float2 f) {
    unsigned r;
    asm("cvt.rn.f16x2.f32 %0, %1, %2;" : "=r"(r) : "f"(f.y), "f"(f.x));
    return r;
}

__device__ __forceinline__ void mma_tf32(float c[4],
                                         unsigned a0, unsigned a1, unsigned a2, unsigned a3,
                                         unsigned b0, unsigned b1) {
    asm volatile(
        "mma.sync.aligned.m16n8k8.row.col.f32.tf32.tf32.f32 "
        "{%0,%1,%2,%3}, {%4,%5,%6,%7}, {%8,%9}, {%0,%1,%2,%3};"
        : "+f"(c[0]), "+f"(c[1]), "+f"(c[2]), "+f"(c[3])
        : "r"(a0), "r"(a1), "r"(a2), "r"(a3), "r"(b0), "r"(b1));
}

__device__ __forceinline__ void mma_f16(float c[4], const unsigned a[4],
                                        unsigned b0, unsigned b1) {
    asm volatile(
        "mma.sync.aligned.m16n8k16.row.col.f32.f16.f16.f32 "
        "{%0,%1,%2,%3}, {%4,%5,%6,%7}, {%8,%9}, {%0,%1,%2,%3};"
        : "+f"(c[0]), "+f"(c[1]), "+f"(c[2]), "+f"(c[3])
        : "r"(a[0]), "r"(a[1]), "r"(a[2]), "r"(a[3]), "r"(b0), "r"(b1));
}

template <int NT>
__device__ __forceinline__ void load_tile_tf32(float* dst, const float* __restrict__ src,
                                               int rows, int tid) {
    for (int idx = tid; idx < TILE * 32; idx += NT) {
        int row = idx >> 5, q = idx & 31;
        float4 v = make_float4(0.f, 0.f, 0.f, 0.f);
        if (row < rows) v = ((const float4*)(src + (size_t)row * 128))[q];
        float4 o = make_float4(cvt_tf32(v.x), cvt_tf32(v.y), cvt_tf32(v.z), cvt_tf32(v.w));
        *((float4*)(dst + row * SA_STRIDE + q * 4)) = o;
    }
}

// async raw-fp32 32x128 tile prefetch into [32][SE_STRIDE] smem, 128 threads
__device__ __forceinline__ void cp_async_tile32(float* sDst, const float* __restrict__ gSrc,
                                                int qtid) {
#pragma unroll
    for (int it = 0; it < 8; it++) {
        int idx = qtid + it * 128;         // 1024 16B-chunks
        int row = idx >> 5, q = idx & 31;
        unsigned saddr = (unsigned)__cvta_generic_to_shared(sDst + row * SE_STRIDE + q * 4);
        asm volatile("cp.async.cg.shared.global [%0], [%1], 16;\n"
                     :: "r"(saddr), "l"(gSrc + (size_t)row * 128 + q * 4));
    }
}

__device__ __forceinline__ void bar_q(int q) {
    asm volatile("bar.sync %0, 128;" :: "r"(q + 1) : "memory");
}

// ---------------- kernel 0: zero output + z accumulators ----------------
__global__ void k_zero(float* __restrict__ out) {
    int i = blockIdx.x * blockDim.x + threadIdx.x;
    const int n_out4 = N_NODES * HD / 4;
    const int n_z4 = N_NODES * NHEADS / 4;
    float4 z = make_float4(0.f, 0.f, 0.f, 0.f);
    if (i < n_out4) ((float4*)out)[i] = z;
    else if (i < n_out4 + n_z4) ((float4*)g_Z)[i - n_out4] = z;
}

// ---------------- kernel 1: QKV projections (tf32, unchanged) -----------
__global__ void __launch_bounds__(512, 1)
k_proj(const float* __restrict__ h,
       const float* __restrict__ Wq, const float* __restrict__ bq,
       const float* __restrict__ Wk, const float* __restrict__ bk,
       const float* __restrict__ Wv, const float* __restrict__ bv) {
    float* smem = (float*)smem_raw;
    float* sA = smem;
    float* sB = sA + TILE * SA_STRIDE;
    float* sBias = sB + TILE * SA_STRIDE;

    const float* W; const float* b; float* outp;
    if (blockIdx.y == 0)      { W = Wq; b = bq; outp = g_Q; }
    else if (blockIdx.y == 1) { W = Wk; b = bk; outp = g_K; }
    else                      { W = Wv; b = bv; outp = g_V; }

    int tid = threadIdx.x;
    int lane = tid & 31, wid = tid >> 5;
    int warp_m = wid & 3, warp_n = wid >> 2;
    int node0 = blockIdx.x * TILE;
    int rows = N_NODES - node0; if (rows > TILE) rows = TILE;

    if (tid < 128) sBias[tid] = b[tid];
    load_tile_tf32<512>(sA, h + (size_t)node0 * 128, rows, tid);
    load_tile_tf32<512>(sB, W, 128, tid);
    __syncthreads();

    float acc[2][4][4];
#pragma unroll
    for (int mt = 0; mt < 2; mt++)
#pragma unroll
        for (int nt = 0; nt < 4; nt++)
#pragma unroll
            for (int i = 0; i < 4; i++) acc[mt][nt][i] = 0.f;

    int gid = lane >> 2, tig = lane & 3;
#pragma unroll
    for (int kk = 0; kk < 16; kk++) {
        int k0 = kk * 8;
        unsigned a[2][4];
#pragma unroll
        for (int mt = 0; mt < 2; mt++) {
            int r = warp_m * 32 + mt * 16 + gid;
            a[mt][0] = __float_as_uint(sA[r * SA_STRIDE + k0 + tig]);
            a[mt][1] = __float_as_uint(sA[(r + 8) * SA_STRIDE + k0 + tig]);
            a[mt][2] = __float_as_uint(sA[r * SA_STRIDE + k0 + tig + 4]);
            a[mt][3] = __float_as_uint(sA[(r + 8) * SA_STRIDE + k0 + tig + 4]);
        }
#pragma unroll
        for (int nt = 0; nt < 4; nt++) {
            int c = warp_n * 32 + nt * 8 + gid;
            unsigned b0 = __float_as_uint(sB[c * SA_STRIDE + k0 + tig]);
            unsigned b1 = __float_as_uint(sB[c * SA_STRIDE + k0 + tig + 4]);
            mma_tf32(acc[0][nt], a[0][0], a[0][1], a[0][2], a[0][3], b0, b1);
            mma_tf32(acc[1][nt], a[1][0], a[1][1], a[1][2], a[1][3], b0, b1);
        }
    }

#pragma unroll
    for (int nt = 0; nt < 4; nt++) {
        int c = warp_n * 32 + nt * 8 + 2 * tig;
        float b0 = sBias[c], b1 = sBias[c + 1];
#pragma unroll
        for (int mt = 0; mt < 2; mt++) {
            int r0 = warp_m * 32 + mt * 16 + gid;
            if (r0 < rows)
                *((float2*)(outp + (size_t)(node0 + r0) * 128 + c)) =
                    make_float2(acc[mt][nt][0] + b0, acc[mt][nt][1] + b1);
            int r1 = r0 + 8;
            if (r1 < rows)
                *((float2*)(outp + (size_t)(node0 + r1) * 128 + c)) =
                    make_float2(acc[mt][nt][2] + b0, acc[mt][nt][3] + b1);
        }
    }
}

// ---------------- kernel 2: quad-pipeline edge kernel, fp16 mma ----------
// 512 threads = four independent 128-thread quarters on private 32-edge tile
// streams. GEMM uses mma.m16n8k16 fp16 (same 11-bit mantissa as tf32):
// halves the mma instruction count vs m16n8k8 tf32.
__global__ void __launch_bounds__(512, 1)
k_edge(const float* __restrict__ e, const int* __restrict__ src, const int* __restrict__ dst,
       const float* __restrict__ We, const float* __restrict__ be, float* __restrict__ out) {
    float* sEb = (float*)smem_raw;                  // 8 bufs [32][136]
    float* sSb = sEb + 8 * TILE_M * SE_STRIDE;      // [4][32*8]
    float* sBe = sSb + 4 * TILE_M * NHEADS;         // [128]
    __half* sWh = (__half*)(sBe + 128);             // [128][144] fp16, k-interleaved
    int* sIdxB = (int*)(sWh + 128 * SWH_STRIDE);    // [4][4][64]

    int tid = threadIdx.x;
    int qtr = tid >> 7, qtid = tid & 127;
    int lane = tid & 31;
    int warp = qtid >> 5;                           // 0..3: 32-col group
    int gid = lane >> 2, tig = lane & 3;

    // stage W as fp16 with per-16 k-interleave: k -> (k&~15) | 4*((k&7)>>1) | (k&1) | 2*((k>>3)&1)
    // so b0 = (k=2tig,2tig+1) and b1 = (k=2tig+8,+9) come from one LDS.64.
    for (int idx = tid; idx < 128 * 128; idx += 512) {
        int c = idx >> 7, k = idx & 127;
        int pc = (k & ~15) | ((((k & 7) >> 1)) << 2) | (k & 1) | (((k >> 3) & 1) << 1);
        sWh[c * SWH_STRIDE + pc] = __float2half_rn(We[idx]);
    }
    if (tid < 128) sBe[tid] = be[tid];
    __syncthreads();   // last block-wide sync; quarters independent below

    float* hE = sEb + qtr * 2 * TILE_M * SE_STRIDE;
    float* hS = sSb + qtr * TILE_M * NHEADS;
    int* hIdx = sIdxB + qtr * 4 * 64;

    const int stride = gridDim.x * 4;
    const int p0 = blockIdx.x * 4 + qtr;

    // prologue: prefetch tiles p0 (buf0), p0+stride (buf1)
    if (p0 < NTILES32) {
        cp_async_tile32(hE, e + (size_t)p0 * TILE_M * 128, qtid);
        if (qtid < 32) {
            hIdx[qtid] = src[p0 * TILE_M + qtid];
            hIdx[32 + qtid] = dst[p0 * TILE_M + qtid];
        }
    }
    asm volatile("cp.async.commit_group;\n" ::: "memory");
    if (p0 + stride < NTILES32) {
        cp_async_tile32(hE + TILE_M * SE_STRIDE, e + (size_t)(p0 + stride) * TILE_M * 128, qtid);
        if (qtid < 32) {
            hIdx[64 + qtid] = src[(p0 + stride) * TILE_M + qtid];
            hIdx[64 + 32 + qtid] = dst[(p0 + stride) * TILE_M + qtid];
        }
    }
    asm volatile("cp.async.commit_group;\n" ::: "memory");

    int k = 0;
    for (int t = p0; t < NTILES32; t += stride, k++) {
        asm volatile("cp.async.wait_group 1;\n" ::: "memory");
        bar_q(qtr);   // tile t + idx visible; prev-iter readers done

        float* sE = hE + (k & 1) * TILE_M * SE_STRIDE;
        const int* sSrc = hIdx + (k & 3) * 64;
        const int* sDst = sSrc + 32;

        // gather K[src]*Q[dst]/sqrt(D) into mma-fragment registers
        float2 kq[2][2][4];
#pragma unroll
        for (int mt = 0; mt < 2; mt++)
#pragma unroll
            for (int rh = 0; rh < 2; rh++) {
                int r = mt * 16 + rh * 8 + gid;
                const float* Kp = g_K + (size_t)sSrc[r] * 128;
                const float* Qp = g_Q + (size_t)sDst[r] * 128;
#pragma unroll
                for (int nt = 0; nt < 4; nt++) {
                    int c = warp * 32 + nt * 8 + 2 * tig;
                    float2 kv = *(const float2*)(Kp + c);
                    float2 qv = *(const float2*)(Qp + c);
                    kq[mt][rh][nt] = make_float2(kv.x * qv.x * 0.25f, kv.y * qv.y * 0.25f);
                }
            }

        float acc[2][4][4];
#pragma unroll
        for (int mt = 0; mt < 2; mt++)
#pragma unroll
            for (int nt = 0; nt < 4; nt++)
#pragma unroll
                for (int i = 0; i < 4; i++) acc[mt][nt][i] = 0.f;

        // 32x128x128 GEMM via fp16 m16n8k16 (8 K-slices of 16)
#pragma unroll
        for (int ks = 0; ks < 8; ks++) {
            int k0 = ks * 16;
            unsigned a[2][4];
#pragma unroll
            for (int mt = 0; mt < 2; mt++) {
                int r = mt * 16 + gid;
                float2 f0 = *(const float2*)(sE + r * SE_STRIDE + k0 + 2 * tig);
                float2 f1 = *(const float2*)(sE + (r + 8) * SE_STRIDE + k0 + 2 * tig);
                float2 f2 = *(const float2*)(sE + r * SE_STRIDE + k0 + 8 + 2 * tig);
                float2 f3 = *(const float2*)(sE + (r + 8) * SE_STRIDE + k0 + 8 + 2 * tig);
                a[mt][0] = cvt_h2(f0); a[mt][1] = cvt_h2(f1);
                a[mt][2] = cvt_h2(f2); a[mt][3] = cvt_h2(f3);
            }
#pragma unroll
            for (int nt = 0; nt < 4; nt++) {
                int c = warp * 32 + nt * 8 + gid;
                uint2 bv = *(const uint2*)(sWh + c * SWH_STRIDE + k0 + 4 * tig);
                mma_f16(acc[0][nt], a[0], bv.x, bv.y);
                mma_f16(acc[1][nt], a[1], bv.x, bv.y);
            }
        }

        // per-head scores: score[e,h] = sum_d KQ * (E + be)
        float part[2][2][2];
#pragma unroll
        for (int mt = 0; mt < 2; mt++)
#pragma unroll
            for (int rh = 0; rh < 2; rh++)
#pragma unroll
                for (int hg = 0; hg < 2; hg++) part[mt][rh][hg] = 0.f;

#pragma unroll
        for (int nt = 0; nt < 4; nt++) {
            int hg = nt >> 1;
            int c = warp * 32 + nt * 8 + 2 * tig;
            float b0 = sBe[c], b1 = sBe[c + 1];
#pragma unroll
            for (int mt = 0; mt < 2; mt++) {
                part[mt][0][hg] += (acc[mt][nt][0] + b0) * kq[mt][0][nt].x
                                 + (acc[mt][nt][1] + b1) * kq[mt][0][nt].y;
                part[mt][1][hg] += (acc[mt][nt][2] + b0) * kq[mt][1][nt].x
                                 + (acc[mt][nt][3] + b1) * kq[mt][1][nt].y;
            }
        }

#pragma unroll
        for (int mt = 0; mt < 2; mt++)
#pragma unroll
            for (int rh = 0; rh < 2; rh++)
#pragma unroll
                for (int hg = 0; hg < 2; hg++) {
                    float p = part[mt][rh][hg];
                    p += __shfl_xor_sync(0xffffffffu, p, 1);
                    p += __shfl_xor_sync(0xffffffffu, p, 2);
                    if (tig == 0) {
                        int row = mt * 16 + rh * 8 + gid;
                        int head = warp * 2 + hg;
                        float sv = __expf(fminf(fmaxf(p, -5.f), 5.f));
                        hS[row * NHEADS + head] = sv;
                        atomicAdd(&g_Z[(size_t)sDst[row] * NHEADS + head], sv);
                    }
                }
        bar_q(qtr);   // hS published; sE GEMM reads complete

        // prefetch tile t+2*stride into the buffer just freed
        int t2 = t + 2 * stride;
        if (t2 < NTILES32) {
            cp_async_tile32(sE, e + (size_t)t2 * TILE_M * 128, qtid);
            if (qtid < 32) {
                int* d = hIdx + ((k + 2) & 3) * 64;
                d[qtid] = src[t2 * TILE_M + qtid];
                d[32 + qtid] = dst[t2 * TILE_M + qtid];
            }
        }
        asm volatile("cp.async.commit_group;\n" ::: "memory");

        // scatter: out[dst] += s * V[src]  (overlaps the cp.async just issued)
#pragma unroll
        for (int it = 0; it < 8; it++) {
            int idx = qtid + it * 128;
            int row = idx >> 5, q = idx & 31;
            int sN = sSrc[row], dN = sDst[row];
            float sc = hS[row * NHEADS + (q >> 2)];
            float4 v = ((const float4*)(g_V + (size_t)sN * 128))[q];
            float4 r = make_float4(v.x * sc, v.y * sc, v.z * sc, v.w * sc);
            atomicAdd((float4*)(out + (size_t)dN * 128 + q * 4), r);
        }
    }
}

// ---------------- kernel 3: normalize -----------------------------------
__global__ void k_final(float* __restrict__ out) {
    int i = blockIdx.x * blockDim.x + threadIdx.x;  // float4 index
    if (i >= N_NODES * HD / 4) return;
    int node = i >> 5;
    int head = (i & 31) >> 2;
    float z = 1.0f / (g_Z[node * NHEADS + head] + 1e-6f);
    float4 v = ((float4*)out)[i];
    v.x *= z; v.y *= z; v.z *= z; v.w *= z;
    ((float4*)out)[i] = v;
}

// ---------------- launcher ------------------------------------------------
extern "C" void kernel_launch(void* const* d_in, const int* in_sizes, int n_in,
                              void* d_out, int out_size) {
    (void)in_sizes; (void)n_in; (void)out_size;
    const float* h  = (const float*)d_in[0];
    const float* e  = (const float*)d_in[1];
    const int*   src = (const int*)d_in[2];
    const int*   dst = (const int*)d_in[3];
    const float* Wq = (const float*)d_in[4];
    const float* bq = (const float*)d_in[5];
    const float* Wk = (const float*)d_in[6];
    const float* bk = (const float*)d_in[7];
    const float* We = (const float*)d_in[8];
    const float* be = (const float*)d_in[9];
    const float* Wv = (const float*)d_in[10];
    const float* bv = (const float*)d_in[11];
    float* out = (float*)d_out;

    cudaFuncSetAttribute(k_proj, cudaFuncAttributeMaxDynamicSharedMemorySize, SMEM_PROJ);
    cudaFuncSetAttribute(k_edge, cudaFuncAttributeMaxDynamicSharedMemorySize, SMEM_EDGE);

    k_zero<<<(N_NODES * HD / 4 + N_NODES * NHEADS / 4 + 255) / 256, 256>>>(out);
    k_proj<<<dim3((N_NODES + TILE - 1) / TILE, 3), 512, SMEM_PROJ>>>(h, Wq, bq, Wk, bk, Wv, bv);
    k_edge<<<EDGE_GRID, 512, SMEM_EDGE>>>(e, src, dst, We, be, out);
    k_final<<<(N_NODES * HD / 4 + 255) / 256, 256>>>(out);
}